// round 16
// baseline (speedup 1.0000x reference)
#include <cuda_runtime.h>

// Problem constants: B=4, C=64, N=512, H=128, 2C=128.
#define B_ 4
#define C_ 64
#define N_ 512
#define H_ 128

typedef unsigned long long u64;

// Scratch (h-major, plain f32):
//   g_A [b][h][n] = b1[h] + sum_c x[b,c,n]*W1[c][h]
//   g_Bv[b][h][n] =         sum_c x[b,c,n]*W1[C+c][h]
//   g_PQp[gy][b][n]: gy 0..3 = P partials (32-h chunks), gy 4..7 = Q partials,
//   with P = sum_h (W2[h]/2)*A, Q = sum_h (W2[h]/2)*Bv.
__device__ float g_A  [B_ * H_ * N_];
__device__ float g_Bv [B_ * H_ * N_];
__device__ float g_PQp[8 * B_ * N_];

// Upper-triangle (It<=Jt) 64x64 tile list, 36 per batch.
__constant__ signed char c_IT[36] = {0,0,0,0,0,0,0,0, 1,1,1,1,1,1,1, 2,2,2,2,2,2,
                                     3,3,3,3,3, 4,4,4,4, 5,5,5, 6,6, 7};
__constant__ signed char c_JT[36] = {0,1,2,3,4,5,6,7, 1,2,3,4,5,6,7, 2,3,4,5,6,7,
                                     3,4,5,6,7, 4,5,6,7, 5,6,7, 6,7, 7};

// ---- packed f32x2 helpers (sm_100+) ----------------------------------------
__device__ __forceinline__ u64 f32x2_add(u64 a, u64 b) {
    u64 r; asm("add.rn.f32x2 %0, %1, %2;" : "=l"(r) : "l"(a), "l"(b)); return r;
}
__device__ __forceinline__ u64 f32x2_fma(u64 a, u64 b, u64 c) {
    u64 r; asm("fma.rn.f32x2 %0, %1, %2, %3;" : "=l"(r) : "l"(a), "l"(b), "l"(c)); return r;
}
__device__ __forceinline__ u64 dup32(float x) {
    u64 r; asm("mov.b64 %0, {%1, %1};" : "=l"(r) : "f"(x)); return r;
}
__device__ __forceinline__ float lo32(u64 v) { return __uint_as_float((unsigned)v); }
__device__ __forceinline__ float hi32(u64 v) { return __uint_as_float((unsigned)(v >> 32)); }
#define ABS2_MASK 0x7FFFFFFF7FFFFFFFULL

// Fire-and-forget vector reduction (sm_90+ / PTX 8.1+): 4 lanes in one REDG.
__device__ __forceinline__ void red_add_v4(float* p, float4 v) {
    asm volatile("red.global.add.v4.f32 [%0], {%1, %2, %3, %4};"
                 :: "l"(p), "f"(v.x), "f"(v.y), "f"(v.z), "f"(v.w) : "memory");
}

// ---------------------------------------------------------------------------
// Kernel 1 (verbatim from R14): 1D grid of 384 blocks, 256 threads.
//   bid < 128:  shared-staged GEMM -> g_A (b1 folded), g_Bv, P/Q partials.
//   bid >= 128: zero 16 KB of out each (4 MB total) -- REDG base + lower tri.
// ---------------------------------------------------------------------------
__global__ void __launch_bounds__(256) precompute_AB(
        const float* __restrict__ x,
        const float* __restrict__ W1,
        const float* __restrict__ b1,
        const float* __restrict__ W2,
        float* __restrict__ out) {
    const int bid = blockIdx.x;
    const int tid = threadIdx.x;

    if (bid >= 128) {   // zero-fill 1024 float4 per block (256 blocks * 16 KB)
        const int z = bid - 128;
        float4* dst = (float4*)out + (size_t)z * 1024;
        const float4 zf = make_float4(0.f, 0.f, 0.f, 0.f);
        #pragma unroll
        for (int r = 0; r < 4; r++)
            dst[tid + 256 * r] = zf;
        return;
    }

    __shared__ float xs[C_ * 128];     // [c][n_loc]  32 KB
    __shared__ float ws[C_ * 32];      // [c][k]       8 KB
    __shared__ float w2s[32];
    __shared__ float b1s[32];
    __shared__ float sPart[4 * 128];   // [hgroup][n_loc] 2 KB

    const int n0  = (bid & 3) * 128;
    const int gy  = (bid >> 2) & 7;    // 0..7
    const int b   = bid >> 5;          // 0..3
    const bool isA = (gy < 4);
    const int h0   = (isA ? gy : gy - 4) * 32;
    const int crow = isA ? 0 : C_;

    const float* xb = x + (size_t)(b * C_) * N_ + n0;
    #pragma unroll
    for (int r = 0; r < 8; r++) {
        int idx = tid + 256 * r;
        int c   = idx >> 5;
        int n4  = idx & 31;
        ((float4*)(xs + c * 128))[n4] = ((const float4*)(xb + (size_t)c * N_))[n4];
    }
    #pragma unroll
    for (int r = 0; r < 2; r++) {
        int idx = tid + 256 * r;
        int c   = idx >> 3;
        int k4  = idx & 7;
        ((float4*)(ws + c * 32))[k4] =
            ((const float4*)(W1 + (size_t)(crow + c) * H_ + h0))[k4];
    }
    if (tid < 32) {
        w2s[tid] = 0.5f * W2[h0 + tid];
        b1s[tid] = isA ? b1[h0 + tid] : 0.0f;
    }
    __syncthreads();

    const int nl0 = (tid & 63) * 2;
    const int hl0 = (tid >> 6) * 8;

    u64 acc[2][4];
    #pragma unroll
    for (int p = 0; p < 2; p++)
        #pragma unroll
        for (int k = 0; k < 4; k++) acc[p][k] = 0ULL;

    #pragma unroll 8
    for (int c = 0; c < C_; c++) {
        float2 xv = *(const float2*)(xs + c * 128 + nl0);
        u64 x0 = dup32(xv.x);
        u64 x1 = dup32(xv.y);
        const ulonglong2* wp = (const ulonglong2*)(ws + c * 32 + hl0);
        ulonglong2 w01 = wp[0];
        ulonglong2 w23 = wp[1];
        acc[0][0] = f32x2_fma(x0, w01.x, acc[0][0]);
        acc[0][1] = f32x2_fma(x0, w01.y, acc[0][1]);
        acc[0][2] = f32x2_fma(x0, w23.x, acc[0][2]);
        acc[0][3] = f32x2_fma(x0, w23.y, acc[0][3]);
        acc[1][0] = f32x2_fma(x1, w01.x, acc[1][0]);
        acc[1][1] = f32x2_fma(x1, w01.y, acc[1][1]);
        acc[1][2] = f32x2_fma(x1, w23.x, acc[1][2]);
        acc[1][3] = f32x2_fma(x1, w23.y, acc[1][3]);
    }

    float* outb = (isA ? g_A : g_Bv) + (size_t)(b * H_ + h0) * N_ + n0 + nl0;
    float p0 = 0.f, p1 = 0.f;
    #pragma unroll
    for (int k = 0; k < 4; k++) {
        #pragma unroll
        for (int s = 0; s < 2; s++) {
            int hl = hl0 + 2 * k + s;
            float bias = b1s[hl];
            float a0 = (s ? hi32(acc[0][k]) : lo32(acc[0][k])) + bias;
            float a1 = (s ? hi32(acc[1][k]) : lo32(acc[1][k])) + bias;
            *(float2*)(outb + (size_t)hl * N_) = make_float2(a0, a1);
            float w = w2s[hl];
            p0 = fmaf(w, a0, p0);
            p1 = fmaf(w, a1, p1);
        }
    }
    sPart[(tid >> 6) * 128 + nl0]     = p0;
    sPart[(tid >> 6) * 128 + nl0 + 1] = p1;
    __syncthreads();
    if (tid < 128) {
        float s = sPart[tid] + sPart[128 + tid] + sPart[256 + tid] + sPart[384 + tid];
        g_PQp[gy * (B_ * N_) + b * N_ + n0 + tid] = s;
    }
}

// ---------------------------------------------------------------------------
// Kernel 2: grid 288 (1D), 256 threads. Output pre-zeroed by k1's fill blocks.
//   bid: hb = bid&1 (h-half), tb = bid>>1, b = tb&3, tl = tb>>2 (upper-tri tile).
//   Each block REDG.ADDs its 64-hh partial (v4); hb==0 also adds P_i+b2+Q_j.
// Thread: 4i x 4j PACKED f32x2: u2 = ADD2(dup(a), (b,b')); acc = FMA2(|u2|, w2, acc)
// with a CONSTANT abs mask (and.b64) that ptxas can fold into the FFMA2 |src|
// modifier. A staged pre-duplicated (broadcast reads anyway); w dup'd in smem.
// Software-pipelined: hh+1 operands prefetched before hh's 16 packed ops.
// ---------------------------------------------------------------------------
__global__ void __launch_bounds__(256) pairwise_score(
        const float* __restrict__ W2,
        const float* __restrict__ b2,
        float* __restrict__ out) {
    const int bid = blockIdx.x;
    const int tid = threadIdx.x;
    const int hb  = bid & 1;          // h-half: 0 -> hh 0..63, 1 -> hh 64..127
    const int tb  = bid >> 1;         // 0..143
    const int b   = tb & 3;
    const int tl  = tb >> 2;          // 0..35
    const int It  = c_IT[tl];
    const int Jt  = c_JT[tl];
    float* outb = out + (size_t)b * N_ * N_;

    __shared__ __align__(16) u64   Adup[65 * 64];  // [hh][ii] dup pairs, +pad row
    __shared__ __align__(16) float Bsh [65 * 64];  // [hh][jj], +pad row
    __shared__ u64   Wsh[66];         // dup(w/2), padded for prefetch
    __shared__ float Psh[64];         // includes b2 (hb==0 only)
    __shared__ float Qsh[64];

    // Stage A (duplicated) and B for this block's 64-hh half.
    const float* Ag = g_A  + (size_t)(b * H_ + hb * 64) * N_ + It * 64;
    const float* Bg = g_Bv + (size_t)(b * H_ + hb * 64) * N_ + Jt * 64;
    #pragma unroll
    for (int r = 0; r < 4; r++) {
        int l  = tid + 256 * r;       // float4 index 0..1023
        int hh = l >> 4;
        int c4 = l & 15;
        float4 va = ((const float4*)(Ag + (size_t)hh * N_))[c4];
        u64* d = Adup + hh * 64 + c4 * 4;
        ((ulonglong2*)d)[0] = make_ulonglong2(dup32(va.x), dup32(va.y));
        ((ulonglong2*)d)[1] = make_ulonglong2(dup32(va.z), dup32(va.w));
        ((float4*)(Bsh + hh * 64))[c4] = ((const float4*)(Bg + (size_t)hh * N_))[c4];
    }
    if (tid < 64) {
        Wsh[tid] = dup32(0.5f * W2[hb * 64 + tid]);
        if (tid == 0) { Wsh[64] = 0ULL; Wsh[65] = 0ULL; }
    } else if (hb == 0) {
        if (tid < 128) {
            int k = tid - 64;         // 0..63
            int n = It * 64 + k;
            Psh[k] = g_PQp[0 * B_ * N_ + b * N_ + n] + g_PQp[1 * B_ * N_ + b * N_ + n]
                   + g_PQp[2 * B_ * N_ + b * N_ + n] + g_PQp[3 * B_ * N_ + b * N_ + n]
                   + b2[0];
        } else if (tid < 192) {
            int k = tid - 128;        // 0..63
            int n = Jt * 64 + k;
            Qsh[k] = g_PQp[4 * B_ * N_ + b * N_ + n] + g_PQp[5 * B_ * N_ + b * N_ + n]
                   + g_PQp[6 * B_ * N_ + b * N_ + n] + g_PQp[7 * B_ * N_ + b * N_ + n];
        }
    }
    __syncthreads();

    const int il0 = (tid >> 4) * 4;   // 0..60
    const int jl0 = (tid & 15) * 4;   // 0..60

    u64 acc[4][2];                    // [p][j-pair]
    #pragma unroll
    for (int p = 0; p < 4; p++) { acc[p][0] = 0ULL; acc[p][1] = 0ULL; }

    const u64*   Ap = Adup + il0;
    const float* Bp = Bsh + jl0;

    // Software-pipelined 64-hh loop: prefetch hh+1 before hh's packed ops.
    ulonglong2 aa01 = *(const ulonglong2*)(Ap);
    ulonglong2 aa23 = *(const ulonglong2*)(Ap + 2);
    ulonglong2 bb   = *(const ulonglong2*)(Bp);
    u64 wc = Wsh[0];
    #pragma unroll 4
    for (int hh = 0; hh < 64; hh++) {
        ulonglong2 an01 = *(const ulonglong2*)(Ap + (hh + 1) * 64);      // pad row
        ulonglong2 an23 = *(const ulonglong2*)(Ap + (hh + 1) * 64 + 2);
        ulonglong2 bn   = *(const ulonglong2*)(Bp + (hh + 1) * 64);
        u64 wn = Wsh[hh + 1];

        u64 a_[4] = {aa01.x, aa01.y, aa23.x, aa23.y};
        #pragma unroll
        for (int p = 0; p < 4; p++) {
            u64 u0 = f32x2_add(a_[p], bb.x) & ABS2_MASK;  // constant mask -> |src| fold
            acc[p][0] = f32x2_fma(u0, wc, acc[p][0]);
            u64 u1 = f32x2_add(a_[p], bb.y) & ABS2_MASK;
            acc[p][1] = f32x2_fma(u1, wc, acc[p][1]);
        }
        aa01 = an01; aa23 = an23; bb = bn; wc = wn;
    }

    const int i0 = It * 64 + il0;
    const int j0 = Jt * 64 + jl0;
    const bool diag = (It == Jt);

    float q_[4] = {0.f, 0.f, 0.f, 0.f}, p_[4] = {0.f, 0.f, 0.f, 0.f};
    if (hb == 0) {
        q_[0] = Qsh[jl0]; q_[1] = Qsh[jl0 + 1]; q_[2] = Qsh[jl0 + 2]; q_[3] = Qsh[jl0 + 3];
        p_[0] = Psh[il0]; p_[1] = Psh[il0 + 1]; p_[2] = Psh[il0 + 2]; p_[3] = Psh[il0 + 3];
    }

    #pragma unroll
    for (int p = 0; p < 4; p++) {
        int i = i0 + p;
        float4 v;
        v.x = lo32(acc[p][0]) + p_[p] + q_[0];
        v.y = hi32(acc[p][0]) + p_[p] + q_[1];
        v.z = lo32(acc[p][1]) + p_[p] + q_[2];
        v.w = hi32(acc[p][1]) + p_[p] + q_[3];
        if (diag) {   // masked lanes contribute 0 (stay 0 from the fill)
            if (!(j0 + 0 > i)) v.x = 0.f;
            if (!(j0 + 1 > i)) v.y = 0.f;
            if (!(j0 + 2 > i)) v.z = 0.f;
            if (!(j0 + 3 > i)) v.w = 0.f;
        }
        red_add_v4(outb + (size_t)i * N_ + j0, v);
    }
}

// ---------------------------------------------------------------------------
// Inputs: 0:x (B,C,N) f32, 1:W1 (2C,H) f32, 2:b1 (H) f32, 3:W2 (H,1) f32,
//         4:b2 (1) f32.  Output: (B,N,N) f32.
// ---------------------------------------------------------------------------
extern "C" void kernel_launch(void* const* d_in, const int* in_sizes, int n_in,
                              void* d_out, int out_size) {
    const float* x  = (const float*)d_in[0];
    const float* W1 = (const float*)d_in[1];
    const float* b1 = (const float*)d_in[2];
    const float* W2 = (const float*)d_in[3];
    const float* b2 = (const float*)d_in[4];
    float* out = (float*)d_out;

    precompute_AB<<<384, 256>>>(x, W1, b1, W2, out);  // 128 GEMM + 256 zero-fill

    pairwise_score<<<288, 256>>>(W2, b2, out);        // 144 tiles x 2 h-halves
}

// round 17
// speedup vs baseline: 1.2163x; 1.2163x over previous
#include <cuda_runtime.h>

// Problem constants: B=4, C=64, N=512, H=128, 2C=128.
#define B_ 4
#define C_ 64
#define N_ 512
#define H_ 128

typedef unsigned long long u64;

// Scratch (h-major, plain f32):
//   g_A [b][h][n] = b1[h] + sum_c x[b,c,n]*W1[c][h]
//   g_Bv[b][h][n] =         sum_c x[b,c,n]*W1[C+c][h]
//   g_PQp[gy][b][n]: gy 0..3 = P partials (32-h chunks), gy 4..7 = Q partials,
//   with P = sum_h (W2[h]/2)*A, Q = sum_h (W2[h]/2)*Bv.
__device__ float g_A  [B_ * H_ * N_];
__device__ float g_Bv [B_ * H_ * N_];
__device__ float g_PQp[8 * B_ * N_];

// Upper-triangle (It<=Jt) 64x64 tile list, 36 per batch.
__constant__ signed char c_IT[36] = {0,0,0,0,0,0,0,0, 1,1,1,1,1,1,1, 2,2,2,2,2,2,
                                     3,3,3,3,3, 4,4,4,4, 5,5,5, 6,6, 7};
__constant__ signed char c_JT[36] = {0,1,2,3,4,5,6,7, 1,2,3,4,5,6,7, 2,3,4,5,6,7,
                                     3,4,5,6,7, 4,5,6,7, 5,6,7, 6,7, 7};

// ---- packed f32x2 helpers (used only in kernel 1) --------------------------
__device__ __forceinline__ u64 f32x2_fma(u64 a, u64 b, u64 c) {
    u64 r; asm("fma.rn.f32x2 %0, %1, %2, %3;" : "=l"(r) : "l"(a), "l"(b), "l"(c)); return r;
}
__device__ __forceinline__ u64 dup32(float x) {
    u64 r; asm("mov.b64 %0, {%1, %1};" : "=l"(r) : "f"(x)); return r;
}
__device__ __forceinline__ float lo32(u64 v) { return __uint_as_float((unsigned)v); }
__device__ __forceinline__ float hi32(u64 v) { return __uint_as_float((unsigned)(v >> 32)); }

// Fire-and-forget vector reduction (sm_90+ / PTX 8.1+): 4 lanes in one REDG.
__device__ __forceinline__ void red_add_v4(float* p, float4 v) {
    asm volatile("red.global.add.v4.f32 [%0], {%1, %2, %3, %4};"
                 :: "l"(p), "f"(v.x), "f"(v.y), "f"(v.z), "f"(v.w) : "memory");
}

// PDL device hooks (sm_90+).
__device__ __forceinline__ void pdl_trigger() {
#if __CUDA_ARCH__ >= 900
    cudaTriggerProgrammaticLaunchCompletion();
#endif
}
__device__ __forceinline__ void pdl_wait() {
#if __CUDA_ARCH__ >= 900
    cudaGridDependencySynchronize();
#endif
}

// ---------------------------------------------------------------------------
// Kernel 1 (R14): 1D grid of 384 blocks, 256 threads.
//   bid < 128:  shared-staged GEMM -> g_A (b1 folded), g_Bv, P/Q partials.
//   bid >= 128: zero 16 KB of out each (4 MB total) -- REDG base + lower tri.
// Each block triggers programmatic launch completion after its last store.
// ---------------------------------------------------------------------------
__global__ void __launch_bounds__(256) precompute_AB(
        const float* __restrict__ x,
        const float* __restrict__ W1,
        const float* __restrict__ b1,
        const float* __restrict__ W2,
        float* __restrict__ out) {
    const int bid = blockIdx.x;
    const int tid = threadIdx.x;

    if (bid >= 128) {   // zero-fill 1024 float4 per block (256 blocks * 16 KB)
        const int z = bid - 128;
        float4* dst = (float4*)out + (size_t)z * 1024;
        const float4 zf = make_float4(0.f, 0.f, 0.f, 0.f);
        #pragma unroll
        for (int r = 0; r < 4; r++)
            dst[tid + 256 * r] = zf;
        pdl_trigger();
        return;
    }

    __shared__ float xs[C_ * 128];     // [c][n_loc]  32 KB
    __shared__ float ws[C_ * 32];      // [c][k]       8 KB
    __shared__ float w2s[32];
    __shared__ float b1s[32];
    __shared__ float sPart[4 * 128];   // [hgroup][n_loc] 2 KB

    const int n0  = (bid & 3) * 128;
    const int gy  = (bid >> 2) & 7;    // 0..7
    const int b   = bid >> 5;          // 0..3
    const bool isA = (gy < 4);
    const int h0   = (isA ? gy : gy - 4) * 32;
    const int crow = isA ? 0 : C_;

    const float* xb = x + (size_t)(b * C_) * N_ + n0;
    #pragma unroll
    for (int r = 0; r < 8; r++) {
        int idx = tid + 256 * r;
        int c   = idx >> 5;
        int n4  = idx & 31;
        ((float4*)(xs + c * 128))[n4] = ((const float4*)(xb + (size_t)c * N_))[n4];
    }
    #pragma unroll
    for (int r = 0; r < 2; r++) {
        int idx = tid + 256 * r;
        int c   = idx >> 3;
        int k4  = idx & 7;
        ((float4*)(ws + c * 32))[k4] =
            ((const float4*)(W1 + (size_t)(crow + c) * H_ + h0))[k4];
    }
    if (tid < 32) {
        w2s[tid] = 0.5f * W2[h0 + tid];
        b1s[tid] = isA ? b1[h0 + tid] : 0.0f;
    }
    __syncthreads();

    const int nl0 = (tid & 63) * 2;
    const int hl0 = (tid >> 6) * 8;

    u64 acc[2][4];
    #pragma unroll
    for (int p = 0; p < 2; p++)
        #pragma unroll
        for (int k = 0; k < 4; k++) acc[p][k] = 0ULL;

    #pragma unroll 8
    for (int c = 0; c < C_; c++) {
        float2 xv = *(const float2*)(xs + c * 128 + nl0);
        u64 x0 = dup32(xv.x);
        u64 x1 = dup32(xv.y);
        const ulonglong2* wp = (const ulonglong2*)(ws + c * 32 + hl0);
        ulonglong2 w01 = wp[0];
        ulonglong2 w23 = wp[1];
        acc[0][0] = f32x2_fma(x0, w01.x, acc[0][0]);
        acc[0][1] = f32x2_fma(x0, w01.y, acc[0][1]);
        acc[0][2] = f32x2_fma(x0, w23.x, acc[0][2]);
        acc[0][3] = f32x2_fma(x0, w23.y, acc[0][3]);
        acc[1][0] = f32x2_fma(x1, w01.x, acc[1][0]);
        acc[1][1] = f32x2_fma(x1, w01.y, acc[1][1]);
        acc[1][2] = f32x2_fma(x1, w23.x, acc[1][2]);
        acc[1][3] = f32x2_fma(x1, w23.y, acc[1][3]);
    }

    float* outb = (isA ? g_A : g_Bv) + (size_t)(b * H_ + h0) * N_ + n0 + nl0;
    float p0 = 0.f, p1 = 0.f;
    #pragma unroll
    for (int k = 0; k < 4; k++) {
        #pragma unroll
        for (int s = 0; s < 2; s++) {
            int hl = hl0 + 2 * k + s;
            float bias = b1s[hl];
            float a0 = (s ? hi32(acc[0][k]) : lo32(acc[0][k])) + bias;
            float a1 = (s ? hi32(acc[1][k]) : lo32(acc[1][k])) + bias;
            *(float2*)(outb + (size_t)hl * N_) = make_float2(a0, a1);
            float w = w2s[hl];
            p0 = fmaf(w, a0, p0);
            p1 = fmaf(w, a1, p1);
        }
    }
    sPart[(tid >> 6) * 128 + nl0]     = p0;
    sPart[(tid >> 6) * 128 + nl0 + 1] = p1;
    __syncthreads();
    if (tid < 128) {
        float s = sPart[tid] + sPart[128 + tid] + sPart[256 + tid] + sPart[384 + tid];
        g_PQp[gy * (B_ * N_) + b * N_ + n0 + tid] = s;
    }
    pdl_trigger();
}

// ---------------------------------------------------------------------------
// Kernel 2 (R14 scalar, + PDL): grid 288, 256 threads. Output pre-zeroed by k1.
//   bid: hb = bid&1 (h-half), tb = bid>>1, b = tb&3, tl = tb>>2 (upper-tri tile).
//   Preamble (index decode + W2 staging) runs BEFORE cudaGridDependencySynchronize;
//   all reads of k1 outputs (g_A/g_Bv/g_PQp) and REDG writes come after.
// Thread: 4i x 4j scalar, FADD+FFMA(|src|), software-pipelined.
// ---------------------------------------------------------------------------
__global__ void __launch_bounds__(256) pairwise_score(
        const float* __restrict__ W2,
        const float* __restrict__ b2,
        float* __restrict__ out) {
    const int bid = blockIdx.x;
    const int tid = threadIdx.x;
    const int hb  = bid & 1;          // h-half: 0 -> hh 0..63, 1 -> hh 64..127
    const int tb  = bid >> 1;         // 0..143
    const int b   = tb & 3;
    const int tl  = tb >> 2;          // 0..35
    const int It  = c_IT[tl];
    const int Jt  = c_JT[tl];
    float* outb = out + (size_t)b * N_ * N_;

    __shared__ __align__(16) float Ash[65 * 64];  // [hh][ii], 1 pad row
    __shared__ __align__(16) float Bsh[65 * 64];  // [hh][jj], 1 pad row
    __shared__ float Wsh[64];         // w/2 for this half
    __shared__ float Psh[64];         // includes b2 (hb==0 only)
    __shared__ float Qsh[64];

    // k1-independent preamble: W2 (a harness input) into shared.
    if (tid < 64)
        Wsh[tid] = 0.5f * W2[hb * 64 + tid];
    const float b2v = b2[0];

    // Wait for k1's writes (g_A, g_Bv, g_PQp, zero-filled out) to be visible.
    pdl_wait();

    // Stage A and B for this block's 64-hh half: 1024 float4 apiece, 4/thread.
    const float* Ag = g_A  + (size_t)(b * H_ + hb * 64) * N_ + It * 64;
    const float* Bg = g_Bv + (size_t)(b * H_ + hb * 64) * N_ + Jt * 64;
    #pragma unroll
    for (int r = 0; r < 4; r++) {
        int l  = tid + 256 * r;       // float4 index 0..1023
        int hh = l >> 4;
        int c4 = l & 15;
        ((float4*)(Ash + hh * 64))[c4] = ((const float4*)(Ag + (size_t)hh * N_))[c4];
        ((float4*)(Bsh + hh * 64))[c4] = ((const float4*)(Bg + (size_t)hh * N_))[c4];
    }
    if (hb == 0) {
        if (tid >= 64 && tid < 128) {
            int k = tid - 64;         // 0..63
            int n = It * 64 + k;
            Psh[k] = g_PQp[0 * B_ * N_ + b * N_ + n] + g_PQp[1 * B_ * N_ + b * N_ + n]
                   + g_PQp[2 * B_ * N_ + b * N_ + n] + g_PQp[3 * B_ * N_ + b * N_ + n]
                   + b2v;
        } else if (tid >= 128 && tid < 192) {
            int k = tid - 128;        // 0..63
            int n = Jt * 64 + k;
            Qsh[k] = g_PQp[4 * B_ * N_ + b * N_ + n] + g_PQp[5 * B_ * N_ + b * N_ + n]
                   + g_PQp[6 * B_ * N_ + b * N_ + n] + g_PQp[7 * B_ * N_ + b * N_ + n];
        }
    }
    __syncthreads();

    const int il0 = (tid >> 4) * 4;   // 0..60
    const int jl0 = (tid & 15) * 4;   // 0..60

    float acc[4][4];
    #pragma unroll
    for (int p = 0; p < 4; p++)
        #pragma unroll
        for (int q = 0; q < 4; q++) acc[p][q] = 0.0f;

    const float* Ap = Ash + il0;
    const float* Bp = Bsh + jl0;

    // Software-pipelined 64-hh loop: prefetch hh+1 before hh's 32 FMAs.
    float4 av = *(const float4*)Ap;
    float4 bv = *(const float4*)Bp;
    #pragma unroll 2
    for (int h4 = 0; h4 < 16; h4++) {
        float4 wv = *(const float4*)(Wsh + h4 * 4);
        #pragma unroll
        for (int k = 0; k < 4; k++) {
            int hh = h4 * 4 + k;
            float4 an = *(const float4*)(Ap + (hh + 1) * 64);  // pad row @64
            float4 bn = *(const float4*)(Bp + (hh + 1) * 64);
            float w = (k == 0) ? wv.x : (k == 1) ? wv.y : (k == 2) ? wv.z : wv.w;
            float a_[4] = {av.x, av.y, av.z, av.w};
            float b_[4] = {bv.x, bv.y, bv.z, bv.w};
            #pragma unroll
            for (int p = 0; p < 4; p++)
                #pragma unroll
                for (int q = 0; q < 4; q++)
                    acc[p][q] = fmaf(fabsf(a_[p] + b_[q]), w, acc[p][q]);
            av = an;
            bv = bn;
        }
    }

    const int i0 = It * 64 + il0;
    const int j0 = Jt * 64 + jl0;
    const bool diag = (It == Jt);

    float q_[4] = {0.f, 0.f, 0.f, 0.f}, p_[4] = {0.f, 0.f, 0.f, 0.f};
    if (hb == 0) {
        q_[0] = Qsh[jl0]; q_[1] = Qsh[jl0 + 1]; q_[2] = Qsh[jl0 + 2]; q_[3] = Qsh[jl0 + 3];
        p_[0] = Psh[il0]; p_[1] = Psh[il0 + 1]; p_[2] = Psh[il0 + 2]; p_[3] = Psh[il0 + 3];
    }

    #pragma unroll
    for (int p = 0; p < 4; p++) {
        int i = i0 + p;
        float4 v;
        v.x = acc[p][0] + p_[p] + q_[0];
        v.y = acc[p][1] + p_[p] + q_[1];
        v.z = acc[p][2] + p_[p] + q_[2];
        v.w = acc[p][3] + p_[p] + q_[3];
        if (diag) {   // masked lanes contribute 0 (stay 0 from the fill)
            if (!(j0 + 0 > i)) v.x = 0.f;
            if (!(j0 + 1 > i)) v.y = 0.f;
            if (!(j0 + 2 > i)) v.z = 0.f;
            if (!(j0 + 3 > i)) v.w = 0.f;
        }
        red_add_v4(outb + (size_t)i * N_ + j0, v);
    }
}

// ---------------------------------------------------------------------------
// Inputs: 0:x (B,C,N) f32, 1:W1 (2C,H) f32, 2:b1 (H) f32, 3:W2 (H,1) f32,
//         4:b2 (1) f32.  Output: (B,N,N) f32.
// ---------------------------------------------------------------------------
extern "C" void kernel_launch(void* const* d_in, const int* in_sizes, int n_in,
                              void* d_out, int out_size) {
    const float* x  = (const float*)d_in[0];
    const float* W1 = (const float*)d_in[1];
    const float* b1 = (const float*)d_in[2];
    const float* W2 = (const float*)d_in[3];
    const float* b2 = (const float*)d_in[4];
    float* out = (float*)d_out;

    precompute_AB<<<384, 256>>>(x, W1, b1, W2, out);  // 128 GEMM + 256 zero-fill

    // k2 with Programmatic Dependent Launch: overlaps its launch + preamble
    // with k1's tail; cudaGridDependencySynchronize() guards all k1 reads.
    cudaLaunchConfig_t cfg = {};
    cfg.gridDim  = dim3(288, 1, 1);
    cfg.blockDim = dim3(256, 1, 1);
    cudaLaunchAttribute attrs[1];
    attrs[0].id = cudaLaunchAttributeProgrammaticStreamSerialization;
    attrs[0].val.programmaticStreamSerializationAllowed = 1;
    cfg.attrs = attrs;
    cfg.numAttrs = 1;
    cudaLaunchKernelEx(&cfg, pairwise_score, W2, b2, out);
}